// round 4
// baseline (speedup 1.0000x reference)
#include <cuda_runtime.h>
#include <cuda_bf16.h>
#include <math.h>
#include <stdint.h>

#define NEGV (-1e10f)
#define KSPAN 1024
#define KANT 50
#define GIDIM 512
#define HID 1000
#define MROWS (KSPAN*KANT)   // 51200
#define KA 1024              // K of big GEMM [gj | gi*gj]
#define NPAD 1024
#define NSLOTS 16
#define W1SCALE 16.0f
#define INVW1 (1.0f/16.0f)

// ---------------- device scratch ----------------
__device__ __nv_bfloat16 d_gb[KSPAN*GIDIM];
__device__ __nv_bfloat16 d_gnb[KSPAN*GIDIM];
__device__ __nv_bfloat16 d_wcb[GIDIM*GIDIM];
__device__ __nv_bfloat16 d_projb[KSPAN*GIDIM];
__device__ float d_ant[KSPAN*KSPAN];
__device__ float d_bs[KSPAN*KANT];
__device__ int   d_bi[KSPAN*KANT];
__device__ unsigned char d_meta[MROWS];
__device__ unsigned char d_A2[(size_t)MROWS*KA];   // e4m3 [gj | gi*gj]
__device__ unsigned char d_B2f[(size_t)NPAD*KA];   // e4m3 W1bc^T * 16
__device__ __nv_bfloat16 d_B1t[(size_t)NPAD*GIDIM];
__device__ __nv_bfloat16 d_wft[(size_t)GIDIM*KA];
__device__ __nv_bfloat16 d_gateA[(size_t)KSPAN*KA];
__device__ float d_Vi[(size_t)KSPAN*NPAD];
__device__ float d_Vc[18*NPAD];
__device__ float d_Vg[8*NPAD];
__device__ float d_w2p[NPAD];
__device__ float d_b1p[NPAD];
__device__ float d_part[(size_t)NSLOTS*MROWS];
__device__ float d_sa[MROWS];
__device__ float d_an[KSPAN*GIDIM];

// ---------------- helpers ----------------
__device__ __forceinline__ uint32_t smem_u32(const void* p){
    uint32_t a; asm("{ .reg .u64 t; cvta.to.shared.u64 t, %1; cvt.u32.u64 %0, t; }" : "=r"(a) : "l"(p));
    return a;
}
__device__ __forceinline__ void cpasync16(uint32_t dst, const void* src){
    asm volatile("cp.async.cg.shared.global [%0], [%1], 16;\n" :: "r"(dst), "l"(src) : "memory");
}
__device__ __forceinline__ unsigned short f2e4m3x2(float lo, float hi){
    unsigned short o;
    asm("cvt.rn.satfinite.e4m3x2.f32 %0, %1, %2;" : "=h"(o) : "f"(hi), "f"(lo));
    return o;
}

// ---------------- prep kernels ----------------
__global__ void prep_gb(const float* __restrict__ g){
    int i = blockIdx.x*256 + threadIdx.x;
    if (i < KSPAN*GIDIM) d_gb[i] = __float2bfloat16(g[i]);
}
__global__ void prep_wcb(const float* __restrict__ W){
    int i = blockIdx.x*256 + threadIdx.x;
    if (i < GIDIM*GIDIM) d_wcb[i] = __float2bfloat16(W[i]);
}
// B2f[n][k] = e4m3( 16 * W1[512+k][n] ), n<HID else 0.  (k<512 -> W1b, k>=512 -> W1c)
__global__ void prep_b2f(const float* __restrict__ W1){
    int idx = blockIdx.x*256 + threadIdx.x;       // pair index
    if (idx >= NPAD*KA/2) return;
    int n = idx / (KA/2), kp = idx - n*(KA/2);
    int k = kp*2;
    float v0 = 0.f, v1 = 0.f;
    if (n < HID){
        v0 = W1SCALE * W1[(size_t)(512+k)*HID + n];
        v1 = W1SCALE * W1[(size_t)(512+k+1)*HID + n];
    }
    ((unsigned short*)d_B2f)[idx] = f2e4m3x2(v0, v1);
}
__global__ void prep_b1t(const float* __restrict__ W1){
    int idx = blockIdx.x*256 + threadIdx.x;
    if (idx >= NPAD*GIDIM) return;
    int n = idx / GIDIM, k = idx - n*GIDIM;
    d_B1t[idx] = __float2bfloat16((n < HID) ? W1[(size_t)k*HID + n] : 0.f);
}
__global__ void prep_wft(const float* __restrict__ Wf){
    int idx = blockIdx.x*256 + threadIdx.x;
    if (idx >= GIDIM*KA) return;
    int n = idx / KA, k = idx - n*KA;
    d_wft[idx] = __float2bfloat16(Wf[(size_t)k*GIDIM + n]);
}
__global__ void prep_vec(const float* __restrict__ b1, const float* __restrict__ W2){
    int n = blockIdx.x*256 + threadIdx.x;
    if (n < NPAD){ d_w2p[n] = (n<HID)? W2[n]:0.f; d_b1p[n] = (n<HID)? b1[n]:0.f; }
}
// rows 0..7 = Vg[genre], rows 8..25 = Vc[bin*2+lab-1]
__global__ void prep_tab(const float* __restrict__ dist_e, const float* __restrict__ genre_e,
                         const float* __restrict__ spk_e, const float* __restrict__ W1){
    int row = blockIdx.x; int n = threadIdx.x;
    float s = 0.f;
    if (n < HID){
        if (row < 8){
            for (int k=0;k<20;k++) s += genre_e[row*20+k]*W1[(size_t)(1556+k)*HID+n];
        } else {
            int c = row-8, bin = c>>1, lab = (c&1)+1;
            for (int k=0;k<20;k++) s += dist_e[bin*20+k]*W1[(size_t)(1536+k)*HID+n]
                                      + spk_e[lab*20+k]*W1[(size_t)(1576+k)*HID+n];
        }
    }
    if (row < 8) d_Vg[row*NPAD+n] = s; else d_Vc[(row-8)*NPAD+n] = s;
}

// ---------------- bf16 mma.sync GEMM (128x128 tile), modes ----------------
// mode0: proj = A@B^T -> d_projb bf16
// mode1: ant  = acc + s[m]+s[n] + mask -> f32
// mode2: Vi   = acc + b1[n] + Vg[gid[m]][n]
// mode3: gate f=sig(acc+bf[n]); d_gnb
__global__ void __launch_bounds__(256) bgemm(int mode, const __nv_bfloat16* __restrict__ A,
        const __nv_bfloat16* __restrict__ B, int Kdim,
        const float* __restrict__ aux0, const float* __restrict__ aux1,
        const int* __restrict__ auxi){
    __shared__ unsigned int sA[2][128*20];
    __shared__ unsigned int sB[2][128*20];
    int n0 = blockIdx.x*128, m0 = blockIdx.y*128;
    int tid = threadIdx.x, lane = tid&31, warp = tid>>5;
    int wm = warp&3, wn = warp>>2;
    float acc[2][8][4];
    #pragma unroll
    for (int a=0;a<2;a++)
        #pragma unroll
        for (int b=0;b<8;b++)
            #pragma unroll
            for (int c=0;c<4;c++) acc[a][b][c]=0.f;
    auto issue = [&](int buf, int kt){
        int k0 = kt*32;
        #pragma unroll
        for (int it=0; it<2; it++){
            int e = tid + it*256, r = e>>2, c = e&3;
            cpasync16(smem_u32(&sA[buf][r*20+c*4]), A + (size_t)(m0+r)*Kdim + k0 + c*8);
            cpasync16(smem_u32(&sB[buf][r*20+c*4]), B + (size_t)(n0+r)*Kdim + k0 + c*8);
        }
        asm volatile("cp.async.commit_group;\n" ::: "memory");
    };
    issue(0,0);
    int KT = Kdim/32;
    for (int kt=0; kt<KT; kt++){
        int buf = kt&1;
        if (kt+1<KT){ issue(buf^1, kt+1); asm volatile("cp.async.wait_group 1;\n" ::: "memory"); }
        else asm volatile("cp.async.wait_group 0;\n" ::: "memory");
        __syncthreads();
        #pragma unroll
        for (int ks=0; ks<2; ks++){
            unsigned int af[2][4], bfr[8][2];
            int arow = wm*32 + (lane>>2), aw = ks*8 + (lane&3);
            #pragma unroll
            for (int mi=0;mi<2;mi++){
                int base = (arow+mi*16)*20;
                af[mi][0]=sA[buf][base+aw]; af[mi][1]=sA[buf][base+160+aw];
                af[mi][2]=sA[buf][base+aw+4]; af[mi][3]=sA[buf][base+160+aw+4];
            }
            int bb = wn*64 + (lane>>2);
            #pragma unroll
            for (int ni=0;ni<8;ni++){
                int base = (bb+ni*8)*20 + aw;
                bfr[ni][0]=sB[buf][base]; bfr[ni][1]=sB[buf][base+4];
            }
            #pragma unroll
            for (int mi=0;mi<2;mi++)
                #pragma unroll
                for (int ni=0;ni<8;ni++)
                    asm volatile("mma.sync.aligned.m16n8k16.row.col.f32.bf16.bf16.f32 "
                        "{%0,%1,%2,%3},{%4,%5,%6,%7},{%8,%9},{%0,%1,%2,%3};\n"
                        : "+f"(acc[mi][ni][0]), "+f"(acc[mi][ni][1]),
                          "+f"(acc[mi][ni][2]), "+f"(acc[mi][ni][3])
                        : "r"(af[mi][0]), "r"(af[mi][1]), "r"(af[mi][2]), "r"(af[mi][3]),
                          "r"(bfr[ni][0]), "r"(bfr[ni][1]));
        }
        __syncthreads();
    }
    #pragma unroll
    for (int mi=0;mi<2;mi++)
        #pragma unroll
        for (int ni=0;ni<8;ni++)
            #pragma unroll
            for (int q=0;q<4;q++){
                int m = m0 + wm*32 + mi*16 + (lane>>2) + ((q>=2)?8:0);
                int n = n0 + wn*64 + ni*8 + (lane&3)*2 + (q&1);
                float v = acc[mi][ni][q];
                if (mode==0) d_projb[(size_t)m*GIDIM+n] = __float2bfloat16(v);
                else if (mode==1){
                    v += aux0[m] + aux0[n];
                    if (n >= m) v += NEGV;
                    d_ant[(size_t)m*KSPAN+n] = v;
                } else if (mode==2){
                    d_Vi[(size_t)m*NPAD+n] = v + d_b1p[n] + d_Vg[auxi[m]*NPAD+n];
                } else {
                    float f = 1.f/(1.f+expf(-(v+aux0[n])));
                    float gv = aux1[(size_t)m*GIDIM+n];
                    float av = d_an[(size_t)m*GIDIM+n];
                    float o = (m==0)? gv : f*gv + (1.f-f)*av;
                    d_gnb[(size_t)m*GIDIM+n] = __float2bfloat16(o);
                }
            }
}

// ---------------- top-K bitonic ----------------
__global__ void topk_kernel(){
    int row = blockIdx.x;
    __shared__ unsigned long long sk[1024];
    for (int j=threadIdx.x; j<1024; j+=512){
        unsigned int b = __float_as_uint(d_ant[(size_t)row*KSPAN+j]);
        unsigned int asc = (b & 0x80000000u) ? ~b : (b | 0x80000000u);
        sk[j] = (((unsigned long long)(~asc))<<32) | (unsigned int)j;
    }
    __syncthreads();
    for (int k=2;k<=1024;k<<=1)
        for (int j=k>>1;j>0;j>>=1){
            for (int i=threadIdx.x;i<1024;i+=512){
                int ixj = i^j;
                if (ixj>i){
                    bool up = ((i&k)==0);
                    unsigned long long a=sk[i], b=sk[ixj];
                    if ((a>b)==up){ sk[i]=b; sk[ixj]=a; }
                }
            }
            __syncthreads();
        }
    if (threadIdx.x < KANT){
        int j = (int)(sk[threadIdx.x] & 0xffffffffu);
        d_bi[row*KANT+threadIdx.x] = j;
        d_bs[row*KANT+threadIdx.x] = d_ant[(size_t)row*KSPAN+j];
    }
}

// ---------------- build A2 (e4m3) = [gj | gi*gj], one warp per row ----------------
__global__ void build_A(int it, const int* __restrict__ starts, const int* __restrict__ ends,
                        const int* __restrict__ sids){
    const __nv_bfloat16* g = it ? d_gnb : d_gb;
    int warp = threadIdx.x>>5, lane = threadIdx.x&31;
    int r = blockIdx.x*8 + warp;
    int i = r/KANT, j = d_bi[r];
    const uint4* gi4 = (const uint4*)(g + (size_t)i*GIDIM);
    const uint4* gj4 = (const uint4*)(g + (size_t)j*GIDIM);
    // lane handles 16 consecutive elements
    uint4 av[2], bv[2];
    av[0] = gi4[lane*2]; av[1] = gi4[lane*2+1];
    bv[0] = gj4[lane*2]; bv[1] = gj4[lane*2+1];
    unsigned int gjw[4], prw[4];
    #pragma unroll
    for (int h=0; h<2; h++){
        const __nv_bfloat162* ap = (const __nv_bfloat162*)&av[h];
        const __nv_bfloat162* bp = (const __nv_bfloat162*)&bv[h];
        #pragma unroll
        for (int w=0; w<2; w++){
            float a0 = __bfloat162float(ap[w*2].x),   a1 = __bfloat162float(ap[w*2].y);
            float a2 = __bfloat162float(ap[w*2+1].x), a3 = __bfloat162float(ap[w*2+1].y);
            float b0 = __bfloat162float(bp[w*2].x),   b1 = __bfloat162float(bp[w*2].y);
            float b2 = __bfloat162float(bp[w*2+1].x), b3 = __bfloat162float(bp[w*2+1].y);
            unsigned int lo = f2e4m3x2(b0,b1), hi = f2e4m3x2(b2,b3);
            gjw[h*2+w] = lo | (hi<<16);
            lo = f2e4m3x2(a0*b0, a1*b1); hi = f2e4m3x2(a2*b2, a3*b3);
            prw[h*2+w] = lo | (hi<<16);
        }
    }
    unsigned char* Ar = d_A2 + (size_t)r*KA;
    ((uint4*)Ar)[lane]        = make_uint4(gjw[0],gjw[1],gjw[2],gjw[3]);
    ((uint4*)(Ar+512))[lane]  = make_uint4(prw[0],prw[1],prw[2],prw[3]);
    if (lane==0){
        int d = ends[i]-starts[j];
        int bin = (d>1)+(d>2)+(d>3)+(d>4)+(d>8)+(d>16)+(d>32)+(d>64);
        int lab = (sids[i]==sids[j]) ? 1 : 2;
        d_meta[r] = (unsigned char)(bin*2 + lab - 1);
    }
}

// ---------------- fp8 MLP GEMM (m16n8k32 e4m3), fused relu+W2 epilogue ----------------
__global__ void __launch_bounds__(256) mlp_f8(){
    __shared__ unsigned int sA[2][128*20];
    __shared__ unsigned int sB[2][128*20];
    int nt = blockIdx.x, n0 = nt*128, m0 = blockIdx.y*128;
    int tid = threadIdx.x, lane = tid&31, warp = tid>>5;
    int wm = warp&3, wn = warp>>2;
    float acc[2][8][4];
    #pragma unroll
    for (int a=0;a<2;a++)
        #pragma unroll
        for (int b=0;b<8;b++)
            #pragma unroll
            for (int c=0;c<4;c++) acc[a][b][c]=0.f;
    auto issue = [&](int buf, int kt){
        int k0 = kt*64;   // 64 bytes (e4m3) per row per chunk
        #pragma unroll
        for (int it=0; it<2; it++){
            int e = tid + it*256, r = e>>2, c = e&3;
            cpasync16(smem_u32(&sA[buf][r*20+c*4]), d_A2  + (size_t)(m0+r)*KA + k0 + c*16);
            cpasync16(smem_u32(&sB[buf][r*20+c*4]), d_B2f + (size_t)(n0+r)*KA + k0 + c*16);
        }
        asm volatile("cp.async.commit_group;\n" ::: "memory");
    };
    issue(0,0);
    const int KT = KA/64;   // 16
    for (int kt=0; kt<KT; kt++){
        int buf = kt&1;
        if (kt+1<KT){ issue(buf^1, kt+1); asm volatile("cp.async.wait_group 1;\n" ::: "memory"); }
        else asm volatile("cp.async.wait_group 0;\n" ::: "memory");
        __syncthreads();
        #pragma unroll
        for (int ks=0; ks<2; ks++){
            unsigned int af[2][4], bfr[8][2];
            int arow = wm*32 + (lane>>2), aw = ks*8 + (lane&3);
            #pragma unroll
            for (int mi=0;mi<2;mi++){
                int base = (arow+mi*16)*20;
                af[mi][0]=sA[buf][base+aw]; af[mi][1]=sA[buf][base+160+aw];
                af[mi][2]=sA[buf][base+aw+4]; af[mi][3]=sA[buf][base+160+aw+4];
            }
            int bb = wn*64 + (lane>>2);
            #pragma unroll
            for (int ni=0;ni<8;ni++){
                int base = (bb+ni*8)*20 + aw;
                bfr[ni][0]=sB[buf][base]; bfr[ni][1]=sB[buf][base+4];
            }
            #pragma unroll
            for (int mi=0;mi<2;mi++)
                #pragma unroll
                for (int ni=0;ni<8;ni++)
                    asm volatile("mma.sync.aligned.m16n8k32.row.col.f32.e4m3.e4m3.f32 "
                        "{%0,%1,%2,%3},{%4,%5,%6,%7},{%8,%9},{%0,%1,%2,%3};\n"
                        : "+f"(acc[mi][ni][0]), "+f"(acc[mi][ni][1]),
                          "+f"(acc[mi][ni][2]), "+f"(acc[mi][ni][3])
                        : "r"(af[mi][0]), "r"(af[mi][1]), "r"(af[mi][2]), "r"(af[mi][3]),
                          "r"(bfr[ni][0]), "r"(bfr[ni][1]));
        }
        __syncthreads();
    }
    // epilogue: h = acc/16 + Vi[i][n] + Vc[meta][n]; rs += relu(h)*w2[n]; reduce over n-quad
    int slot = nt*2 + wn;
    #pragma unroll
    for (int mi=0;mi<2;mi++){
        int mA = m0 + wm*32 + mi*16 + (lane>>2);
        int mB = mA + 8;
        int iA = mA/KANT, iB = mB/KANT;
        const float* ViA = d_Vi + (size_t)iA*NPAD;
        const float* ViB = d_Vi + (size_t)iB*NPAD;
        const float* VcA = d_Vc + (size_t)d_meta[mA]*NPAD;
        const float* VcB = d_Vc + (size_t)d_meta[mB]*NPAD;
        float rs0 = 0.f, rs1 = 0.f;
        #pragma unroll
        for (int ni=0;ni<8;ni++){
            int n = n0 + wn*64 + ni*8 + (lane&3)*2;
            float w2a = d_w2p[n], w2b = d_w2p[n+1];
            float h;
            h = acc[mi][ni][0]*INVW1 + __ldg(ViA+n)   + __ldg(VcA+n);   rs0 += fmaxf(h,0.f)*w2a;
            h = acc[mi][ni][1]*INVW1 + __ldg(ViA+n+1) + __ldg(VcA+n+1); rs0 += fmaxf(h,0.f)*w2b;
            h = acc[mi][ni][2]*INVW1 + __ldg(ViB+n)   + __ldg(VcB+n);   rs1 += fmaxf(h,0.f)*w2a;
            h = acc[mi][ni][3]*INVW1 + __ldg(ViB+n+1) + __ldg(VcB+n+1); rs1 += fmaxf(h,0.f)*w2b;
        }
        rs0 += __shfl_xor_sync(0xffffffffu, rs0, 1);
        rs0 += __shfl_xor_sync(0xffffffffu, rs0, 2);
        rs1 += __shfl_xor_sync(0xffffffffu, rs1, 1);
        rs1 += __shfl_xor_sync(0xffffffffu, rs1, 2);
        if ((lane&3)==0){
            d_part[(size_t)slot*MROWS + mA] = rs0;
            d_part[(size_t)slot*MROWS + mB] = rs1;
        }
    }
}

__global__ void reduce_sa(){
    int m = blockIdx.x*256 + threadIdx.x;
    if (m >= MROWS) return;
    float s = 0.f;
    #pragma unroll
    for (int t=0; t<NSLOTS; t++) s += d_part[(size_t)t*MROWS + m];
    d_sa[m] = s;
}

// ---------------- refinement ----------------
__global__ void refine_kernel(const float* __restrict__ g, const float* __restrict__ b2){
    int i = blockIdx.x;
    int nv = min(i, KANT);
    __shared__ float p[KANT+1];
    __shared__ int ji[KANT];
    __shared__ float red[128];
    int tid = threadIdx.x;
    float val;
    if (tid==0) val = 0.f;
    else if (tid<=KANT){
        int kk = tid-1;
        val = (kk<nv) ? d_sa[i*KANT+kk] + b2[0] + d_bs[i*KANT+kk] : NEGV;
    } else val = NEGV;
    red[tid]=val; __syncthreads();
    for (int s=64;s>0;s>>=1){ if (tid<s) red[tid]=fmaxf(red[tid],red[tid+s]); __syncthreads(); }
    float mx = red[0]; __syncthreads();
    float e = (tid<=KANT) ? expf(val-mx) : 0.f;
    red[tid]=e; __syncthreads();
    for (int s=64;s>0;s>>=1){ if (tid<s) red[tid]+=red[tid+s]; __syncthreads(); }
    float sum = red[0];
    if (tid<=KANT) p[tid] = e/sum;
    if (tid<KANT) ji[tid] = d_bi[i*KANT+tid];
    __syncthreads();
    for (int d=tid; d<GIDIM; d+=128){
        float a = p[0]*g[(size_t)i*GIDIM+d];
        for (int kk=0;kk<nv;kk++) a += p[kk+1]*g[(size_t)ji[kk]*GIDIM+d];
        d_an[(size_t)i*GIDIM+d] = a;
    }
}

__global__ void build_gateA(const float* __restrict__ g){
    int idx = blockIdx.x*256 + threadIdx.x;
    if (idx >= KSPAN*GIDIM) return;
    int m = idx/GIDIM, d = idx - m*GIDIM;
    d_gateA[(size_t)m*KA + d]         = __float2bfloat16(g[idx]);
    d_gateA[(size_t)m*KA + GIDIM + d] = __float2bfloat16(d_an[idx]);
}

__global__ void final_kernel(const float* __restrict__ b2, float* __restrict__ out){
    int idx = blockIdx.x*256 + threadIdx.x;
    if (idx >= KSPAN*(KANT+1)) return;
    int i = idx/(KANT+1), c = idx - i*(KANT+1);
    float v;
    if (c==0) v = 0.f;
    else {
        int kk = c-1;
        if (i==0) v = (kk==0)? 0.f : NEGV;
        else      v = (kk < min(i,KANT)) ? d_sa[i*KANT+kk] + b2[0] + d_bs[i*KANT+kk] : NEGV;
    }
    out[idx] = v;
}

// ---------------- launch ----------------
extern "C" void kernel_launch(void* const* d_in, const int* in_sizes, int n_in,
                              void* d_out, int out_size){
    const float* g_i     = (const float*)d_in[0];
    const float* mention = (const float*)d_in[1];
    const float* dist_e  = (const float*)d_in[2];
    const float* genre_e = (const float*)d_in[3];
    const float* spk_e   = (const float*)d_in[4];
    const float* coarseW = (const float*)d_in[5];
    const float* W1      = (const float*)d_in[6];
    const float* b1      = (const float*)d_in[7];
    const float* W2      = (const float*)d_in[8];
    const float* b2      = (const float*)d_in[9];
    const float* Wf      = (const float*)d_in[10];
    const float* bfv     = (const float*)d_in[11];
    const int* starts    = (const int*)d_in[12];
    const int* ends      = (const int*)d_in[13];
    const int* gids      = (const int*)d_in[14];
    const int* sids      = (const int*)d_in[15];
    float* out = (float*)d_out;

    prep_gb<<<(KSPAN*GIDIM+255)/256,256>>>(g_i);
    prep_wcb<<<(GIDIM*GIDIM+255)/256,256>>>(coarseW);
    prep_b2f<<<(NPAD*KA/2+255)/256,256>>>(W1);
    prep_b1t<<<(NPAD*GIDIM+255)/256,256>>>(W1);
    prep_wft<<<(GIDIM*KA+255)/256,256>>>(Wf);
    prep_vec<<<(NPAD+255)/256,256>>>(b1, W2);
    prep_tab<<<26,1024>>>(dist_e, genre_e, spk_e, W1);

    bgemm<<<dim3(GIDIM/128, KSPAN/128),256>>>(0, d_gb, d_wcb, GIDIM, nullptr, nullptr, nullptr);
    bgemm<<<dim3(KSPAN/128, KSPAN/128),256>>>(1, d_projb, d_gb, GIDIM, mention, nullptr, nullptr);
    topk_kernel<<<KSPAN,512>>>();

    for (int it=0; it<2; it++){
        const __nv_bfloat16* gcur = it ? d_gnb : d_gb;
        bgemm<<<dim3(NPAD/128, KSPAN/128),256>>>(2, gcur, d_B1t, GIDIM, nullptr, nullptr, gids);
        build_A<<<MROWS/8,256>>>(it, starts, ends, sids);
        mlp_f8<<<dim3(NPAD/128, MROWS/128),256>>>();
        reduce_sa<<<(MROWS+255)/256,256>>>();
        if (it==0){
            refine_kernel<<<KSPAN,128>>>(g_i, b2);
            build_gateA<<<(KSPAN*GIDIM+255)/256,256>>>(g_i);
            bgemm<<<dim3(GIDIM/128, KSPAN/128),256>>>(3, d_gateA, d_wft, KA, bfv, g_i, nullptr);
        } else {
            final_kernel<<<(KSPAN*(KANT+1)+255)/256,256>>>(b2, out);
        }
    }
}